// round 9
// baseline (speedup 1.0000x reference)
#include <cuda_runtime.h>
#include <cuda_fp16.h>
#include <cooperative_groups.h>
#include <math.h>

namespace cg = cooperative_groups;

#define N_NODES 50000
#define N_EDGES 1600000
#define D 128
#define NET 8
#define K_HOPS 10

#define CB ((N_NODES * D / 4 + 255) / 256)  // cvt blocks

// ---- static scratch ----
__device__ __half g_h16A[N_NODES * D];
__device__ __half g_h16B[N_NODES * D];
__device__ __half g_f016[N_NODES * D];   // fp16(feat) for residual
__device__ int   g_meta[N_EDGES + 64];   // src | (etype<<16), CSR-ordered by dst
__device__ int   g_ptr[N_NODES + 1];
__device__ int   g_indeg[N_NODES];
__device__ int   g_outdeg[N_NODES];
__device__ int   g_fill[N_NODES];
__device__ float g_srcnorm[N_NODES];
__device__ float2 g_abZ[N_NODES];        // {0.9*dn*sn, 0.1*sn}  -> writes z = h*sn
__device__ float2 g_abH[N_NODES];        // {0.9*dn,    0.1   }  -> writes h (last hop)
__device__ float g_gate[NET];            // 1 + sigmoid(MLP(embed[t]))

__device__ __forceinline__ float gelu_exact(float x) {
    return 0.5f * x * (1.0f + erff(x * 0.70710678118654752440f));
}

// ---------------- launch 0: zero counters ----------------
__global__ void k_zero() {
    int i = blockIdx.x * blockDim.x + threadIdx.x;
    if (i < N_NODES) { g_indeg[i] = 0; g_outdeg[i] = 0; g_fill[i] = 0; }
}

// ---------------- launch 1: degree count ----------------
__global__ void k_deg(const int* __restrict__ src, const int* __restrict__ dst) {
    int e = blockIdx.x * blockDim.x + threadIdx.x;
    if (e < N_EDGES) {
        atomicAdd(&g_outdeg[src[e]], 1);
        atomicAdd(&g_indeg[dst[e]], 1);
    }
}

// ---------------- launch 2: prefix scan of indeg -> CSR ptr, + norms fused ----------
__global__ void k_scan() {
    __shared__ int sm[1024];
    int t = threadIdx.x;
    const int CH = (N_NODES + 1023) / 1024;   // 49
    int beg = t * CH, end = min(beg + CH, N_NODES);
    int s = 0;
    for (int i = beg; i < end; i++) {
        int id = g_indeg[i];
        s += id;
        float sn = rsqrtf(fmaxf((float)g_outdeg[i], 1.0f));
        float dn = rsqrtf(fmaxf((float)id, 1.0f));
        g_srcnorm[i] = sn;
        g_abZ[i] = make_float2(0.9f * dn * sn, 0.1f * sn);
        g_abH[i] = make_float2(0.9f * dn, 0.1f);
    }
    sm[t] = s;
    __syncthreads();
    for (int d = 1; d < 1024; d <<= 1) {
        int add = (t >= d) ? sm[t - d] : 0;
        __syncthreads();
        sm[t] += add;
        __syncthreads();
    }
    int off = sm[t] - s;
    for (int i = beg; i < end; i++) { g_ptr[i] = off; off += g_indeg[i]; }
    if (t == 1023) g_ptr[N_NODES] = off;
}

// ---------------- launch 3 (PROFILED SLOT): bucket edges by dst ----------------
__global__ void k_scatter(const int* __restrict__ src, const int* __restrict__ dst,
                          const int* __restrict__ ef) {
    int e = blockIdx.x * blockDim.x + threadIdx.x;
    if (e < N_EDGES) {
        int d = dst[e];
        int pos = g_ptr[d] + atomicAdd(&g_fill[d], 1);
        g_meta[pos] = src[e] | (ef[e] << 16);   // src < 65536, etype < 8
    }
}

// ---------------- launch 4: z0 = fp16(feat*srcnorm), f016 = fp16(feat), + gate ------
__global__ void k_cvtgate(const float* __restrict__ feat,
                          const float* __restrict__ emb, const float* __restrict__ We1,
                          const float* __restrict__ be1, const float* __restrict__ We2,
                          const float* __restrict__ be2) {
    int b = blockIdx.x, tid = threadIdx.x;
    if (b < CB) {
        int i = b * 256 + tid;
        if (i < N_NODES * D / 4) {
            int row = i >> 5;                       // (i*4)/128
            float sn = g_srcnorm[row];
            float4 v = *(const float4*)(feat + i * 4);
            __half2 a = __floats2half2_rn(v.x, v.y);
            __half2 c = __floats2half2_rn(v.z, v.w);
            uint2 u;  u.x = *(unsigned int*)&a;  u.y = *(unsigned int*)&c;
            *(uint2*)(g_f016 + i * 4) = u;
            __half2 za = __floats2half2_rn(v.x * sn, v.y * sn);
            __half2 zc = __floats2half2_rn(v.z * sn, v.w * sn);
            uint2 zu; zu.x = *(unsigned int*)&za; zu.y = *(unsigned int*)&zc;
            *(uint2*)(g_h16A + i * 4) = zu;         // z0 lives in buffer A
        }
    } else {
        int w = tid >> 5, lane = tid & 31;
        if (w < NET) {
            float acc = be1[lane];
            #pragma unroll 8
            for (int i = 0; i < D; i++)
                acc = fmaf(emb[w * D + i], We1[i * 32 + lane], acc);
            float g = gelu_exact(acc);
            float v = g * We2[lane];
            #pragma unroll
            for (int o = 16; o; o >>= 1) v += __shfl_down_sync(0xffffffffu, v, o);
            if (lane == 0)
                g_gate[w] = 1.0f + 1.0f / (1.0f + expf(-(v + be2[0])));
        }
    }
}

// ---------------- persistent 10-hop kernel: warp per node, grid.sync between hops ----
__device__ __forceinline__ void accp2(unsigned long long* a, float cbc, uint4 u) {
    unsigned long long c2;
    asm("mov.b64 %0, {%1, %1};" : "=l"(c2) : "f"(cbc));
    __half2* hp = (__half2*)&u;
    #pragma unroll
    for (int q = 0; q < 4; q++) {
        float2 f = __half22float2(hp[q]);
        unsigned long long v;
        asm("mov.b64 %0, {%1, %2};" : "=l"(v) : "f"(f.x), "f"(f.y));
        asm("fma.rn.f32x2 %0, %1, %2, %0;" : "+l"(a[q]) : "l"(v), "l"(c2));
    }
}

__device__ __forceinline__ void hop_node(int gw, int lane, int half, int col,
                                         float gate_reg,
                                         const __half* __restrict__ z_in,
                                         __half* __restrict__ h_out,
                                         const float2* __restrict__ ab) {
    int beg = g_ptr[gw], end = g_ptr[gw + 1];
    unsigned long long acc[4] = {0ull, 0ull, 0ull, 0ull};

    for (int e0 = beg; e0 < end; e0 += 32) {
        int m = min(32, end - e0);
        int mv = (lane < m) ? g_meta[e0 + lane] : 0;
        int ssrc = mv & 0xffff;
        float gv = __shfl_sync(0xffffffffu, gate_reg, (mv >> 16) & 7);
        float cl = (lane < m) ? gv : 0.0f;        // inactive lanes contribute 0
        int i = 0;
        for (; i + 8 <= m; i += 8) {              // 4 pairs = 8 edges, 4 LDG.128 in flight
            int i0 = i + half, i1 = i + 2 + half, i2 = i + 4 + half, i3 = i + 6 + half;
            int   s0 = __shfl_sync(0xffffffffu, ssrc, i0);
            int   s1 = __shfl_sync(0xffffffffu, ssrc, i1);
            int   s2 = __shfl_sync(0xffffffffu, ssrc, i2);
            int   s3 = __shfl_sync(0xffffffffu, ssrc, i3);
            float c0 = __shfl_sync(0xffffffffu, cl, i0);
            float c1 = __shfl_sync(0xffffffffu, cl, i1);
            float c2 = __shfl_sync(0xffffffffu, cl, i2);
            float c3 = __shfl_sync(0xffffffffu, cl, i3);
            uint4 u0 = *(const uint4*)(z_in + s0 * D + col);
            uint4 u1 = *(const uint4*)(z_in + s1 * D + col);
            uint4 u2 = *(const uint4*)(z_in + s2 * D + col);
            uint4 u3 = *(const uint4*)(z_in + s3 * D + col);
            accp2(acc, c0, u0);
            accp2(acc, c1, u1);
            accp2(acc, c2, u2);
            accp2(acc, c3, u3);
        }
        for (; i < m; i += 2) {                   // tail pairs
            int i0 = i + half;
            int   s0 = __shfl_sync(0xffffffffu, ssrc, i0);
            float c0 = __shfl_sync(0xffffffffu, cl, i0);
            uint4 u0 = *(const uint4*)(z_in + s0 * D + col);
            accp2(acc, c0, u0);
        }
    }

    float r[8];
    #pragma unroll
    for (int q = 0; q < 4; q++)
        asm("mov.b64 {%0, %1}, %2;" : "=f"(r[2 * q]), "=f"(r[2 * q + 1]) : "l"(acc[q]));
    #pragma unroll
    for (int j = 0; j < 8; j++)
        r[j] += __shfl_xor_sync(0xffffffffu, r[j], 16);

    if (half == 0) {
        float2 av = ab[gw];
        uint4 fu = *(const uint4*)(g_f016 + gw * D + col);
        __half2* fp = (__half2*)&fu;
        uint4 ou;
        unsigned int* op = (unsigned int*)&ou;
        #pragma unroll
        for (int q = 0; q < 4; q++) {
            float2 f = __half22float2(fp[q]);
            __half2 o = __floats2half2_rn(fmaf(av.x, r[2 * q],     av.y * f.x),
                                          fmaf(av.x, r[2 * q + 1], av.y * f.y));
            op[q] = *(unsigned int*)&o;
        }
        *(uint4*)(h_out + gw * D + col) = ou;
    }
}

__global__ void __launch_bounds__(256, 5) k_hops(__half* __restrict__ bufA,
                                                 __half* __restrict__ bufB,
                                                 const float2* __restrict__ abZ,
                                                 const float2* __restrict__ abH) {
    cg::grid_group grid = cg::this_grid();
    int lane = threadIdx.x & 31;
    int half = lane >> 4;
    int col  = (lane & 15) * 8;
    float gate_reg = g_gate[lane & 7];
    int warpG = (blockIdx.x * blockDim.x + threadIdx.x) >> 5;
    int nW    = (gridDim.x * blockDim.x) >> 5;

    const __half* zin = bufA;     // z0 in A
    __half* hout = bufB;
    #pragma unroll 1
    for (int k = 0; k < K_HOPS; k++) {
        const float2* ab = (k == K_HOPS - 1) ? abH : abZ;
        for (int gw = warpG; gw < N_NODES; gw += nW)
            hop_node(gw, lane, half, col, gate_reg, zin, hout, ab);
        grid.sync();
        const __half* t = zin;
        zin  = hout;
        hout = (__half*)t;
    }
    // after 10 hops the final h is in bufA (even # of swaps from A-start)
}

// ---------------- fused output MLP with packed f32x2 FMA ----------------
#define MLP_ROWS 64
#define WS_STRIDE 132
#define XS_STRIDE 136

union WU { float4 f4; unsigned long long u[2]; };

__global__ void __launch_bounds__(256) k_mlp(const __half* __restrict__ x,
                                             const float* __restrict__ W1,
                                             const float* __restrict__ b1,
                                             const float* __restrict__ W2,
                                             const float* __restrict__ b2,
                                             float* __restrict__ out) {
    extern __shared__ float smem[];
    float* Ws = smem;                           // 128 x 132
    float* xs = smem + 128 * WS_STRIDE;         // 64 x 136
    float* ts = xs + MLP_ROWS * XS_STRIDE;      // 64 x 136
    int tid = threadIdx.x;
    int row0 = blockIdx.x * MLP_ROWS;

    for (int idx = tid; idx < 128 * 128; idx += 256)
        Ws[(idx >> 7) * WS_STRIDE + (idx & 127)] = W1[idx];
    for (int idx = tid; idx < MLP_ROWS * 64; idx += 256) {
        int r = idx >> 6, c2 = idx & 63, gr = row0 + r;
        float2 v = make_float2(0.f, 0.f);
        if (gr < N_NODES) {
            __half2 h = *(const __half2*)(x + gr * D + c2 * 2);
            v = __half22float2(h);
        }
        xs[r * XS_STRIDE + c2 * 2]     = v.x;
        xs[r * XS_STRIDE + c2 * 2 + 1] = v.y;
    }
    __syncthreads();

    int rg = tid >> 4, cg2 = tid & 15;
    int r0 = rg * 4, c0 = cg2 * 8;
    unsigned long long acc2[4][4];
    #pragma unroll
    for (int i = 0; i < 4; i++)
        #pragma unroll
        for (int q = 0; q < 4; q++) acc2[i][q] = 0ull;

    #pragma unroll 4
    for (int k = 0; k < 128; k++) {
        WU w0, w1;
        w0.f4 = *(const float4*)&Ws[k * WS_STRIDE + c0];
        w1.f4 = *(const float4*)&Ws[k * WS_STRIDE + c0 + 4];
        unsigned long long B[4] = {w0.u[0], w0.u[1], w1.u[0], w1.u[1]};
        #pragma unroll
        for (int i = 0; i < 4; i++) {
            float a = xs[(r0 + i) * XS_STRIDE + k];
            unsigned long long a2;
            asm("mov.b64 %0, {%1, %1};" : "=l"(a2) : "f"(a));
            #pragma unroll
            for (int q = 0; q < 4; q++)
                asm("fma.rn.f32x2 %0, %1, %2, %0;" : "+l"(acc2[i][q]) : "l"(a2), "l"(B[q]));
        }
    }
    #pragma unroll
    for (int i = 0; i < 4; i++)
        #pragma unroll
        for (int q = 0; q < 4; q++) {
            float lo, hi;
            asm("mov.b64 {%0, %1}, %2;" : "=f"(lo), "=f"(hi) : "l"(acc2[i][q]));
            ts[(r0 + i) * XS_STRIDE + c0 + 2 * q]     = gelu_exact(lo + b1[c0 + 2 * q]);
            ts[(r0 + i) * XS_STRIDE + c0 + 2 * q + 1] = gelu_exact(hi + b1[c0 + 2 * q + 1]);
        }
    __syncthreads();
    for (int idx = tid; idx < 128 * 128; idx += 256)
        Ws[(idx >> 7) * WS_STRIDE + (idx & 127)] = W2[idx];
    #pragma unroll
    for (int i = 0; i < 4; i++)
        #pragma unroll
        for (int q = 0; q < 4; q++) acc2[i][q] = 0ull;
    __syncthreads();

    #pragma unroll 4
    for (int k = 0; k < 128; k++) {
        WU w0, w1;
        w0.f4 = *(const float4*)&Ws[k * WS_STRIDE + c0];
        w1.f4 = *(const float4*)&Ws[k * WS_STRIDE + c0 + 4];
        unsigned long long B[4] = {w0.u[0], w0.u[1], w1.u[0], w1.u[1]};
        #pragma unroll
        for (int i = 0; i < 4; i++) {
            float a = ts[(r0 + i) * XS_STRIDE + k];
            unsigned long long a2;
            asm("mov.b64 %0, {%1, %1};" : "=l"(a2) : "f"(a));
            #pragma unroll
            for (int q = 0; q < 4; q++)
                asm("fma.rn.f32x2 %0, %1, %2, %0;" : "+l"(acc2[i][q]) : "l"(a2), "l"(B[q]));
        }
    }
    #pragma unroll
    for (int i = 0; i < 4; i++) {
        int gr = row0 + r0 + i;
        if (gr < N_NODES) {
            #pragma unroll
            for (int q = 0; q < 4; q++) {
                float lo, hi;
                asm("mov.b64 {%0, %1}, %2;" : "=f"(lo), "=f"(hi) : "l"(acc2[i][q]));
                out[gr * D + c0 + 2 * q]     = lo + b2[c0 + 2 * q];
                out[gr * D + c0 + 2 * q + 1] = hi + b2[c0 + 2 * q + 1];
            }
        }
    }
}

// ---------------- launch ----------------
extern "C" void kernel_launch(void* const* d_in, const int* in_sizes, int n_in,
                              void* d_out, int out_size) {
    const float* feat  = (const float*)d_in[0];
    const int*   e_ft  = (const int*)  d_in[1];
    const int*   src   = (const int*)  d_in[2];
    const int*   dst   = (const int*)  d_in[3];
    const float* emb   = (const float*)d_in[4];
    const float* We1   = (const float*)d_in[5];
    const float* be1   = (const float*)d_in[6];
    const float* We2   = (const float*)d_in[7];
    const float* be2   = (const float*)d_in[8];
    const float* W1    = (const float*)d_in[9];
    const float* b1    = (const float*)d_in[10];
    const float* W2    = (const float*)d_in[11];
    const float* b2    = (const float*)d_in[12];
    float* out = (float*)d_out;

    k_zero<<<(N_NODES + 255) / 256, 256>>>();                           // 0
    k_deg<<<(N_EDGES + 255) / 256, 256>>>(src, dst);                    // 1
    k_scan<<<1, 1024>>>();                                              // 2 (+norms)
    k_scatter<<<(N_EDGES + 255) / 256, 256>>>(src, dst, e_ft);          // 3  <- profiled
    k_cvtgate<<<CB + 1, 256>>>(feat, emb, We1, be1, We2, be2);          // 4

    __half *hA = nullptr, *hB = nullptr;
    float2 *abZ = nullptr, *abH = nullptr;
    cudaGetSymbolAddress((void**)&hA, g_h16A);
    cudaGetSymbolAddress((void**)&hB, g_h16B);
    cudaGetSymbolAddress((void**)&abZ, g_abZ);
    cudaGetSymbolAddress((void**)&abH, g_abH);

    // persistent cooperative 10-hop kernel, exactly-resident grid
    int dev = 0, nsm = 0, nb = 0;
    cudaGetDevice(&dev);
    cudaDeviceGetAttribute(&nsm, cudaDevAttrMultiProcessorCount, dev);
    cudaOccupancyMaxActiveBlocksPerMultiprocessor(&nb, (const void*)k_hops, 256, 0);
    if (nb < 1) nb = 1;
    int grid = nsm * nb;
    void* args[] = {&hA, &hB, &abZ, &abH};
    cudaLaunchCooperativeKernel((const void*)k_hops, dim3(grid), dim3(256), args, 0, (cudaStream_t)0);

    size_t smem_bytes = (size_t)(128 * WS_STRIDE + 2 * MLP_ROWS * XS_STRIDE) * sizeof(float);
    cudaFuncSetAttribute(k_mlp, cudaFuncAttributeMaxDynamicSharedMemorySize, (int)smem_bytes);
    k_mlp<<<(N_NODES + MLP_ROWS - 1) / MLP_ROWS, 256, smem_bytes>>>(hA, W1, b1, W2, b2, out);
}

// round 10
// speedup vs baseline: 1.8014x; 1.8014x over previous
#include <cuda_runtime.h>
#include <cuda_fp16.h>
#include <mma.h>
#include <math.h>

using namespace nvcuda;

#define N_NODES 50000
#define N_EDGES 1600000
#define D 128
#define NET 8
#define K_HOPS 10

#define CB ((N_NODES * D / 4 + 255) / 256)  // cvt blocks

// ---- static scratch ----
__device__ __half g_h16A[N_NODES * D];
__device__ __half g_h16B[N_NODES * D];
__device__ __half g_f016[N_NODES * D];   // fp16(feat) for residual
__device__ int   g_meta[N_EDGES + 64];   // src | (etype<<16), CSR-ordered by dst
__device__ int   g_ptr[N_NODES + 1];
__device__ int   g_indeg[N_NODES];
__device__ int   g_outdeg[N_NODES];
__device__ int   g_fill[N_NODES];
__device__ float g_srcnorm[N_NODES];
__device__ float2 g_abZ[N_NODES];        // {0.9*dn*sn, 0.1*sn}  -> writes z = h*sn
__device__ float2 g_abH[N_NODES];        // {0.9*dn,    0.1   }  -> writes h (last hop)
__device__ float g_gate[NET];            // 1 + sigmoid(MLP(embed[t]))
__device__ __half g_W1h[D * D];          // fp16 copies of MLP weights
__device__ __half g_W2h[D * D];

__device__ __forceinline__ float gelu_exact(float x) {
    return 0.5f * x * (1.0f + erff(x * 0.70710678118654752440f));
}

// ---------------- launch 0: zero counters ----------------
__global__ void k_zero() {
    int i = blockIdx.x * blockDim.x + threadIdx.x;
    if (i < N_NODES) { g_indeg[i] = 0; g_outdeg[i] = 0; g_fill[i] = 0; }
}

// ---------------- launch 1: degree count ----------------
__global__ void k_deg(const int* __restrict__ src, const int* __restrict__ dst) {
    int e = blockIdx.x * blockDim.x + threadIdx.x;
    if (e < N_EDGES) {
        atomicAdd(&g_outdeg[src[e]], 1);
        atomicAdd(&g_indeg[dst[e]], 1);
    }
}

// ---------------- launch 2: exclusive prefix scan of indeg -> CSR ptr ----------------
__global__ void k_scan() {
    __shared__ int sm[1024];
    int t = threadIdx.x;
    const int CH = (N_NODES + 1023) / 1024;   // 49
    int beg = t * CH, end = min(beg + CH, N_NODES);
    int s = 0;
    for (int i = beg; i < end; i++) s += g_indeg[i];
    sm[t] = s;
    __syncthreads();
    for (int d = 1; d < 1024; d <<= 1) {
        int add = (t >= d) ? sm[t - d] : 0;
        __syncthreads();
        sm[t] += add;
        __syncthreads();
    }
    int off = sm[t] - s;
    for (int i = beg; i < end; i++) { g_ptr[i] = off; off += g_indeg[i]; }
    if (t == 1023) g_ptr[N_NODES] = off;
}

// ---------------- launch 3 (PROFILED SLOT): bucket edges by dst ----------------
__global__ void k_scatter(const int* __restrict__ src, const int* __restrict__ dst,
                          const int* __restrict__ ef) {
    int e = blockIdx.x * blockDim.x + threadIdx.x;
    if (e < N_EDGES) {
        int d = dst[e];
        int pos = g_ptr[d] + atomicAdd(&g_fill[d], 1);
        g_meta[pos] = src[e] | (ef[e] << 16);   // src < 65536, etype < 8
    }
}

// ---------------- launch 4: norms + epilogue coefficient pairs ----------------
__global__ void k_norm() {
    int i = blockIdx.x * blockDim.x + threadIdx.x;
    if (i < N_NODES) {
        float sn = rsqrtf(fmaxf((float)g_outdeg[i], 1.0f));
        float dn = rsqrtf(fmaxf((float)g_indeg[i], 1.0f));
        g_srcnorm[i] = sn;
        g_abZ[i] = make_float2(0.9f * dn * sn, 0.1f * sn);
        g_abH[i] = make_float2(0.9f * dn, 0.1f);
    }
}

// ------- launch 5: z0/f016 converts + W1/W2 -> fp16 + edge gate, one fused grid -------
__global__ void k_cvtgate(const float* __restrict__ feat,
                          const float* __restrict__ W1, const float* __restrict__ W2,
                          const float* __restrict__ emb, const float* __restrict__ We1,
                          const float* __restrict__ be1, const float* __restrict__ We2,
                          const float* __restrict__ be2) {
    int b = blockIdx.x, tid = threadIdx.x;
    if (b < CB) {
        int i = b * 256 + tid;
        if (i < N_NODES * D / 4) {
            int row = i >> 5;                       // (i*4)/128
            float sn = g_srcnorm[row];
            float4 v = *(const float4*)(feat + i * 4);
            __half2 a = __floats2half2_rn(v.x, v.y);
            __half2 c = __floats2half2_rn(v.z, v.w);
            uint2 u;  u.x = *(unsigned int*)&a;  u.y = *(unsigned int*)&c;
            *(uint2*)(g_f016 + i * 4) = u;
            __half2 za = __floats2half2_rn(v.x * sn, v.y * sn);
            __half2 zc = __floats2half2_rn(v.z * sn, v.w * sn);
            uint2 zu; zu.x = *(unsigned int*)&za; zu.y = *(unsigned int*)&zc;
            *(uint2*)(g_h16A + i * 4) = zu;         // z0 lives in buffer A
        }
    } else if (b < CB + 64) {
        int i = (b - CB) * 256 + tid;               // 64*256 = 16384 = D*D
        g_W1h[i] = __float2half_rn(W1[i]);
    } else if (b < CB + 128) {
        int i = (b - CB - 64) * 256 + tid;
        g_W2h[i] = __float2half_rn(W2[i]);
    } else {
        int w = tid >> 5, lane = tid & 31;
        if (w < NET) {
            float acc = be1[lane];
            #pragma unroll 8
            for (int i = 0; i < D; i++)
                acc = fmaf(emb[w * D + i], We1[i * 32 + lane], acc);
            float g = gelu_exact(acc);
            float v = g * We2[lane];
            #pragma unroll
            for (int o = 16; o; o >>= 1) v += __shfl_down_sync(0xffffffffu, v, o);
            if (lane == 0)
                g_gate[w] = 1.0f + 1.0f / (1.0f + expf(-(v + be2[0])));
        }
    }
}

// ---------------- hop: warp per dst node, 2 edges/LDG.128, packed f32x2 FMA ------------
__device__ __forceinline__ void accp2(unsigned long long* a, float cbc, uint4 u) {
    unsigned long long c2;
    asm("mov.b64 %0, {%1, %1};" : "=l"(c2) : "f"(cbc));
    __half2* hp = (__half2*)&u;
    #pragma unroll
    for (int q = 0; q < 4; q++) {
        float2 f = __half22float2(hp[q]);
        unsigned long long v;
        asm("mov.b64 %0, {%1, %2};" : "=l"(v) : "f"(f.x), "f"(f.y));
        asm("fma.rn.f32x2 %0, %1, %2, %0;" : "+l"(a[q]) : "l"(v), "l"(c2));
    }
}

__global__ void __launch_bounds__(256, 5) k_hop(const __half* __restrict__ z_in,
                                                __half* __restrict__ h_out,
                                                const float2* __restrict__ ab) {
    int gw   = (blockIdx.x * blockDim.x + threadIdx.x) >> 5;  // node id
    int lane = threadIdx.x & 31;
    if (gw >= N_NODES) return;
    int beg = g_ptr[gw], end = g_ptr[gw + 1];
    int half = lane >> 4;
    int col  = (lane & 15) * 8;                   // 8 halves (16 B) per lane
    float gate_reg = g_gate[lane & 7];            // 8 gate values resident in warp

    unsigned long long acc[4] = {0ull, 0ull, 0ull, 0ull};

    for (int e0 = beg; e0 < end; e0 += 32) {
        int m = min(32, end - e0);
        int mv = (lane < m) ? g_meta[e0 + lane] : 0;
        int ssrc = mv & 0xffff;
        float gv = __shfl_sync(0xffffffffu, gate_reg, (mv >> 16) & 7);
        float cl = (lane < m) ? gv : 0.0f;        // inactive lanes contribute 0
        int i = 0;
        for (; i + 8 <= m; i += 8) {              // 4 pairs = 8 edges, 4 LDG.128 in flight
            int i0 = i + half, i1 = i + 2 + half, i2 = i + 4 + half, i3 = i + 6 + half;
            int   s0 = __shfl_sync(0xffffffffu, ssrc, i0);
            int   s1 = __shfl_sync(0xffffffffu, ssrc, i1);
            int   s2 = __shfl_sync(0xffffffffu, ssrc, i2);
            int   s3 = __shfl_sync(0xffffffffu, ssrc, i3);
            float c0 = __shfl_sync(0xffffffffu, cl, i0);
            float c1 = __shfl_sync(0xffffffffu, cl, i1);
            float c2 = __shfl_sync(0xffffffffu, cl, i2);
            float c3 = __shfl_sync(0xffffffffu, cl, i3);
            uint4 u0 = *(const uint4*)(z_in + s0 * D + col);
            uint4 u1 = *(const uint4*)(z_in + s1 * D + col);
            uint4 u2 = *(const uint4*)(z_in + s2 * D + col);
            uint4 u3 = *(const uint4*)(z_in + s3 * D + col);
            accp2(acc, c0, u0);
            accp2(acc, c1, u1);
            accp2(acc, c2, u2);
            accp2(acc, c3, u3);
        }
        for (; i < m; i += 2) {                   // tail pairs (lanes >= m have cl = 0)
            int i0 = i + half;
            int   s0 = __shfl_sync(0xffffffffu, ssrc, i0);
            float c0 = __shfl_sync(0xffffffffu, cl, i0);
            uint4 u0 = *(const uint4*)(z_in + s0 * D + col);
            accp2(acc, c0, u0);
        }
    }

    float r[8];
    #pragma unroll
    for (int q = 0; q < 4; q++)
        asm("mov.b64 {%0, %1}, %2;" : "=f"(r[2 * q]), "=f"(r[2 * q + 1]) : "l"(acc[q]));
    #pragma unroll
    for (int j = 0; j < 8; j++)
        r[j] += __shfl_xor_sync(0xffffffffu, r[j], 16);

    if (half == 0) {
        float2 av = ab[gw];
        uint4 fu = *(const uint4*)(g_f016 + gw * D + col);
        __half2* fp = (__half2*)&fu;
        uint4 ou;
        unsigned int* op = (unsigned int*)&ou;
        #pragma unroll
        for (int q = 0; q < 4; q++) {
            float2 f = __half22float2(fp[q]);
            __half2 o = __floats2half2_rn(fmaf(av.x, r[2 * q],     av.y * f.x),
                                          fmaf(av.x, r[2 * q + 1], av.y * f.y));
            op[q] = *(unsigned int*)&o;
        }
        *(uint4*)(h_out + gw * D + col) = ou;
    }
}

// ---------------- output MLP via wmma HMMA: gelu(x@W1+b1)@W2+b2 ----------------
// 64 rows per block, 8 warps: warp (rw = w&3, ch = w>>2) -> rows rw*16, cols ch*64.
#define MROWS 64
#define LDH 136   // halves (= floats) leading dim, padded

__global__ void __launch_bounds__(256) k_mlp(const __half* __restrict__ x,
                                             const __half* __restrict__ W1h,
                                             const float* __restrict__ b1,
                                             const __half* __restrict__ W2h,
                                             const float* __restrict__ b2,
                                             float* __restrict__ out) {
    extern __shared__ __half smh[];
    __half* Ws = smh;                         // 128 x LDH halves
    __half* xs = smh + 128 * LDH;             // 64 x LDH halves
    float*  fs = (float*)(xs + MROWS * LDH);  // 64 x LDH floats
    int tid = threadIdx.x, w = tid >> 5;
    int row0 = blockIdx.x * MROWS;
    int rw = w & 3, ch = w >> 2;

    // stage W1 and x
    for (int i = tid; i < 128 * 128; i += 256)
        Ws[(i >> 7) * LDH + (i & 127)] = W1h[i];
    for (int i = tid; i < MROWS * 16; i += 256) {     // uint4 = 8 halves
        int r = i >> 4, c8 = i & 15, gr = row0 + r;
        uint4 v = make_uint4(0u, 0u, 0u, 0u);
        if (gr < N_NODES) v = *(const uint4*)(x + gr * D + c8 * 8);
        *(uint4*)(xs + r * LDH + c8 * 8) = v;
    }
    __syncthreads();

    // gemm1: t = x @ W1
    wmma::fragment<wmma::accumulator, 16, 16, 16, float> acc[4];
    #pragma unroll
    for (int j = 0; j < 4; j++) wmma::fill_fragment(acc[j], 0.0f);
    #pragma unroll
    for (int k0 = 0; k0 < 128; k0 += 16) {
        wmma::fragment<wmma::matrix_a, 16, 16, 16, __half, wmma::row_major> af;
        wmma::load_matrix_sync(af, xs + rw * 16 * LDH + k0, LDH);
        #pragma unroll
        for (int j = 0; j < 4; j++) {
            wmma::fragment<wmma::matrix_b, 16, 16, 16, __half, wmma::row_major> bf;
            wmma::load_matrix_sync(bf, Ws + k0 * LDH + ch * 64 + j * 16, LDH);
            wmma::mma_sync(acc[j], af, bf, acc[j]);
        }
    }
    #pragma unroll
    for (int j = 0; j < 4; j++)
        wmma::store_matrix_sync(fs + rw * 16 * LDH + ch * 64 + j * 16, acc[j], LDH,
                                wmma::mem_row_major);
    __syncthreads();

    // gelu(t + b1) -> xs (fp16), and stage W2
    for (int i = tid; i < MROWS * 128; i += 256) {
        int r = i >> 7, c = i & 127;
        xs[r * LDH + c] = __float2half_rn(gelu_exact(fs[r * LDH + c] + b1[c]));
    }
    for (int i = tid; i < 128 * 128; i += 256)
        Ws[(i >> 7) * LDH + (i & 127)] = W2h[i];
    __syncthreads();

    // gemm2: out = t @ W2
    #pragma unroll
    for (int j = 0; j < 4; j++) wmma::fill_fragment(acc[j], 0.0f);
    #pragma unroll
    for (int k0 = 0; k0 < 128; k0 += 16) {
        wmma::fragment<wmma::matrix_a, 16, 16, 16, __half, wmma::row_major> af;
        wmma::load_matrix_sync(af, xs + rw * 16 * LDH + k0, LDH);
        #pragma unroll
        for (int j = 0; j < 4; j++) {
            wmma::fragment<wmma::matrix_b, 16, 16, 16, __half, wmma::row_major> bf;
            wmma::load_matrix_sync(bf, Ws + k0 * LDH + ch * 64 + j * 16, LDH);
            wmma::mma_sync(acc[j], af, bf, acc[j]);
        }
    }
    #pragma unroll
    for (int j = 0; j < 4; j++)
        wmma::store_matrix_sync(fs + rw * 16 * LDH + ch * 64 + j * 16, acc[j], LDH,
                                wmma::mem_row_major);
    __syncthreads();

    for (int i = tid; i < MROWS * 128; i += 256) {
        int r = i >> 7, c = i & 127, gr = row0 + r;
        if (gr < N_NODES) out[gr * D + c] = fs[r * LDH + c] + b2[c];
    }
}

// ---------------- launch ----------------
extern "C" void kernel_launch(void* const* d_in, const int* in_sizes, int n_in,
                              void* d_out, int out_size) {
    const float* feat  = (const float*)d_in[0];
    const int*   e_ft  = (const int*)  d_in[1];
    const int*   src   = (const int*)  d_in[2];
    const int*   dst   = (const int*)  d_in[3];
    const float* emb   = (const float*)d_in[4];
    const float* We1   = (const float*)d_in[5];
    const float* be1   = (const float*)d_in[6];
    const float* We2   = (const float*)d_in[7];
    const float* be2   = (const float*)d_in[8];
    const float* W1    = (const float*)d_in[9];
    const float* b1    = (const float*)d_in[10];
    const float* W2    = (const float*)d_in[11];
    const float* b2    = (const float*)d_in[12];
    float* out = (float*)d_out;

    k_zero<<<(N_NODES + 255) / 256, 256>>>();                           // 0
    k_deg<<<(N_EDGES + 255) / 256, 256>>>(src, dst);                    // 1
    k_scan<<<1, 1024>>>();                                              // 2
    k_scatter<<<(N_EDGES + 255) / 256, 256>>>(src, dst, e_ft);          // 3  <- profiled
    k_norm<<<(N_NODES + 255) / 256, 256>>>();                           // 4
    k_cvtgate<<<CB + 129, 256>>>(feat, W1, W2, emb, We1, be1, We2, be2);// 5

    __half *hA = nullptr, *hB = nullptr, *w1h = nullptr, *w2h = nullptr;
    float2 *abZ = nullptr, *abH = nullptr;
    cudaGetSymbolAddress((void**)&hA, g_h16A);
    cudaGetSymbolAddress((void**)&hB, g_h16B);
    cudaGetSymbolAddress((void**)&abZ, g_abZ);
    cudaGetSymbolAddress((void**)&abH, g_abH);
    cudaGetSymbolAddress((void**)&w1h, g_W1h);
    cudaGetSymbolAddress((void**)&w2h, g_W2h);

    const __half* zin = hA;       // z0 in buffer A
    __half* hout = hB;
    int hop_blocks = (N_NODES * 32 + 255) / 256;
    for (int k = 0; k < K_HOPS; k++) {
        const float2* ab = (k == K_HOPS - 1) ? abH : abZ;
        k_hop<<<hop_blocks, 256>>>(zin, hout, ab);
        zin  = hout;
        hout = (hout == hA) ? hB : hA;
    }

    size_t smem_bytes = (size_t)(128 * LDH + MROWS * LDH) * sizeof(__half)
                      + (size_t)(MROWS * LDH) * sizeof(float);
    cudaFuncSetAttribute(k_mlp, cudaFuncAttributeMaxDynamicSharedMemorySize, (int)smem_bytes);
    k_mlp<<<(N_NODES + MROWS - 1) / MROWS, 256, smem_bytes>>>(zin, w1h, b1, w2h, b2, out);
}

// round 11
// speedup vs baseline: 2.2177x; 1.2311x over previous
#include <cuda_runtime.h>
#include <cuda_fp16.h>
#include <mma.h>
#include <math.h>

using namespace nvcuda;

#define N_NODES 50000
#define N_EDGES 1600000
#define D 128
#define NET 8
#define K_HOPS 10

#define CB ((N_NODES * D / 4 + 255) / 256)  // cvt blocks

// ---- static scratch ----
__device__ __half g_h16A[N_NODES * D];
__device__ __half g_h16B[N_NODES * D];
__device__ __half g_f016[N_NODES * D];   // fp16(feat) for residual
__device__ int   g_meta[N_EDGES + 64];   // src | (etype<<16), CSR-ordered by dst
__device__ int   g_ptr[N_NODES + 1];
__device__ int   g_indeg[N_NODES];
__device__ int   g_outdeg[N_NODES];
__device__ int   g_fill[N_NODES];
__device__ float g_srcnorm[N_NODES];
__device__ float2 g_abZ[N_NODES];        // {0.9*dn*sn, 0.1*sn}  -> writes z = h*sn
__device__ float2 g_abH[N_NODES];        // {0.9*dn,    0.1   }  -> writes h (last hop)
__device__ float g_gate[NET];            // 1 + sigmoid(MLP(embed[t]))
__device__ __half g_W1h[D * D];          // fp16 copies of MLP weights
__device__ __half g_W2h[D * D];

__device__ __forceinline__ float gelu_exact(float x) {
    return 0.5f * x * (1.0f + erff(x * 0.70710678118654752440f));
}

// ---------------- launch 0: zero counters ----------------
__global__ void k_zero() {
    int i = blockIdx.x * blockDim.x + threadIdx.x;
    if (i < N_NODES) { g_indeg[i] = 0; g_outdeg[i] = 0; g_fill[i] = 0; }
}

// ---------------- launch 1: degree count ----------------
__global__ void k_deg(const int* __restrict__ src, const int* __restrict__ dst) {
    int e = blockIdx.x * blockDim.x + threadIdx.x;
    if (e < N_EDGES) {
        atomicAdd(&g_outdeg[src[e]], 1);
        atomicAdd(&g_indeg[dst[e]], 1);
    }
}

// ---------------- launch 2: prefix scan of indeg -> CSR ptr, + norms fused ----------
__global__ void k_scan() {
    __shared__ int sm[1024];
    int t = threadIdx.x;
    const int CH = (N_NODES + 1023) / 1024;   // 49
    int beg = t * CH, end = min(beg + CH, N_NODES);
    int s = 0;
    for (int i = beg; i < end; i++) {
        int id = g_indeg[i];
        s += id;
        float sn = rsqrtf(fmaxf((float)g_outdeg[i], 1.0f));
        float dn = rsqrtf(fmaxf((float)id, 1.0f));
        g_srcnorm[i] = sn;
        g_abZ[i] = make_float2(0.9f * dn * sn, 0.1f * sn);
        g_abH[i] = make_float2(0.9f * dn, 0.1f);
    }
    sm[t] = s;
    __syncthreads();
    for (int d = 1; d < 1024; d <<= 1) {
        int add = (t >= d) ? sm[t - d] : 0;
        __syncthreads();
        sm[t] += add;
        __syncthreads();
    }
    int off = sm[t] - s;
    for (int i = beg; i < end; i++) { g_ptr[i] = off; off += g_indeg[i]; }
    if (t == 1023) g_ptr[N_NODES] = off;
}

// ---------------- launch 3 (PROFILED SLOT): bucket edges by dst ----------------
__global__ void k_scatter(const int* __restrict__ src, const int* __restrict__ dst,
                          const int* __restrict__ ef) {
    int e = blockIdx.x * blockDim.x + threadIdx.x;
    if (e < N_EDGES) {
        int d = dst[e];
        int pos = g_ptr[d] + atomicAdd(&g_fill[d], 1);
        g_meta[pos] = src[e] | (ef[e] << 16);   // src < 65536, etype < 8
    }
}

// ------- launch 4: z0/f016 converts + W1/W2 -> fp16 + edge gate, one fused grid -------
__global__ void k_cvtgate(const float* __restrict__ feat,
                          const float* __restrict__ W1, const float* __restrict__ W2,
                          const float* __restrict__ emb, const float* __restrict__ We1,
                          const float* __restrict__ be1, const float* __restrict__ We2,
                          const float* __restrict__ be2) {
    int b = blockIdx.x, tid = threadIdx.x;
    if (b < CB) {
        int i = b * 256 + tid;
        if (i < N_NODES * D / 4) {
            int row = i >> 5;                       // (i*4)/128
            float sn = g_srcnorm[row];
            float4 v = *(const float4*)(feat + i * 4);
            __half2 a = __floats2half2_rn(v.x, v.y);
            __half2 c = __floats2half2_rn(v.z, v.w);
            uint2 u;  u.x = *(unsigned int*)&a;  u.y = *(unsigned int*)&c;
            *(uint2*)(g_f016 + i * 4) = u;
            __half2 za = __floats2half2_rn(v.x * sn, v.y * sn);
            __half2 zc = __floats2half2_rn(v.z * sn, v.w * sn);
            uint2 zu; zu.x = *(unsigned int*)&za; zu.y = *(unsigned int*)&zc;
            *(uint2*)(g_h16A + i * 4) = zu;         // z0 lives in buffer A
        }
    } else if (b < CB + 64) {
        int i = (b - CB) * 256 + tid;               // 64*256 = 16384 = D*D
        g_W1h[i] = __float2half_rn(W1[i]);
    } else if (b < CB + 128) {
        int i = (b - CB - 64) * 256 + tid;
        g_W2h[i] = __float2half_rn(W2[i]);
    } else {
        int w = tid >> 5, lane = tid & 31;
        if (w < NET) {
            float acc = be1[lane];
            #pragma unroll 8
            for (int i = 0; i < D; i++)
                acc = fmaf(emb[w * D + i], We1[i * 32 + lane], acc);
            float g = gelu_exact(acc);
            float v = g * We2[lane];
            #pragma unroll
            for (int o = 16; o; o >>= 1) v += __shfl_down_sync(0xffffffffu, v, o);
            if (lane == 0)
                g_gate[w] = 1.0f + 1.0f / (1.0f + expf(-(v + be2[0])));
        }
    }
}

// ---------------- hop: warp per dst node, 2 edges/LDG.128, packed f32x2 FMA ------------
__device__ __forceinline__ void accp2(unsigned long long* a, float cbc, uint4 u) {
    unsigned long long c2;
    asm("mov.b64 %0, {%1, %1};" : "=l"(c2) : "f"(cbc));
    __half2* hp = (__half2*)&u;
    #pragma unroll
    for (int q = 0; q < 4; q++) {
        float2 f = __half22float2(hp[q]);
        unsigned long long v;
        asm("mov.b64 %0, {%1, %2};" : "=l"(v) : "f"(f.x), "f"(f.y));
        asm("fma.rn.f32x2 %0, %1, %2, %0;" : "+l"(a[q]) : "l"(v), "l"(c2));
    }
}

__global__ void __launch_bounds__(256, 5) k_hop(const __half* __restrict__ z_in,
                                                __half* __restrict__ h_out,
                                                const float2* __restrict__ ab) {
    int gw   = (blockIdx.x * blockDim.x + threadIdx.x) >> 5;  // node id
    int lane = threadIdx.x & 31;
    if (gw >= N_NODES) return;
    int beg = g_ptr[gw], end = g_ptr[gw + 1];
    int half = lane >> 4;
    int col  = (lane & 15) * 8;                   // 8 halves (16 B) per lane
    float gate_reg = g_gate[lane & 7];            // 8 gate values resident in warp

    unsigned long long acc[4] = {0ull, 0ull, 0ull, 0ull};

    for (int e0 = beg; e0 < end; e0 += 32) {
        int m = min(32, end - e0);
        int mv = (lane < m) ? g_meta[e0 + lane] : 0;
        int ssrc = mv & 0xffff;
        float gv = __shfl_sync(0xffffffffu, gate_reg, (mv >> 16) & 7);
        float cl = (lane < m) ? gv : 0.0f;        // inactive lanes contribute 0
        int i = 0;
        for (; i + 8 <= m; i += 8) {              // 4 pairs = 8 edges, 4 LDG.128 in flight
            int i0 = i + half, i1 = i + 2 + half, i2 = i + 4 + half, i3 = i + 6 + half;
            int   s0 = __shfl_sync(0xffffffffu, ssrc, i0);
            int   s1 = __shfl_sync(0xffffffffu, ssrc, i1);
            int   s2 = __shfl_sync(0xffffffffu, ssrc, i2);
            int   s3 = __shfl_sync(0xffffffffu, ssrc, i3);
            float c0 = __shfl_sync(0xffffffffu, cl, i0);
            float c1 = __shfl_sync(0xffffffffu, cl, i1);
            float c2 = __shfl_sync(0xffffffffu, cl, i2);
            float c3 = __shfl_sync(0xffffffffu, cl, i3);
            uint4 u0 = *(const uint4*)(z_in + s0 * D + col);
            uint4 u1 = *(const uint4*)(z_in + s1 * D + col);
            uint4 u2 = *(const uint4*)(z_in + s2 * D + col);
            uint4 u3 = *(const uint4*)(z_in + s3 * D + col);
            accp2(acc, c0, u0);
            accp2(acc, c1, u1);
            accp2(acc, c2, u2);
            accp2(acc, c3, u3);
        }
        for (; i < m; i += 2) {                   // tail pairs (lanes >= m have cl = 0)
            int i0 = i + half;
            int   s0 = __shfl_sync(0xffffffffu, ssrc, i0);
            float c0 = __shfl_sync(0xffffffffu, cl, i0);
            uint4 u0 = *(const uint4*)(z_in + s0 * D + col);
            accp2(acc, c0, u0);
        }
    }

    float r[8];
    #pragma unroll
    for (int q = 0; q < 4; q++)
        asm("mov.b64 {%0, %1}, %2;" : "=f"(r[2 * q]), "=f"(r[2 * q + 1]) : "l"(acc[q]));
    #pragma unroll
    for (int j = 0; j < 8; j++)
        r[j] += __shfl_xor_sync(0xffffffffu, r[j], 16);

    if (half == 0) {
        float2 av = ab[gw];
        uint4 fu = *(const uint4*)(g_f016 + gw * D + col);
        __half2* fp = (__half2*)&fu;
        uint4 ou;
        unsigned int* op = (unsigned int*)&ou;
        #pragma unroll
        for (int q = 0; q < 4; q++) {
            float2 f = __half22float2(fp[q]);
            __half2 o = __floats2half2_rn(fmaf(av.x, r[2 * q],     av.y * f.x),
                                          fmaf(av.x, r[2 * q + 1], av.y * f.y));
            op[q] = *(unsigned int*)&o;
        }
        *(uint4*)(h_out + gw * D + col) = ou;
    }
}

// ---------------- output MLP via wmma HMMA: gelu(x@W1+b1)@W2+b2 ----------------
// 64 rows per block, 8 warps: warp (rw = w&3, ch = w>>2) -> rows rw*16, cols ch*64.
#define MROWS 64
#define LDH 136   // halves (= floats) leading dim, padded

__global__ void __launch_bounds__(256) k_mlp(const __half* __restrict__ x,
                                             const __half* __restrict__ W1h,
                                             const float* __restrict__ b1,
                                             const __half* __restrict__ W2h,
                                             const float* __restrict__ b2,
                                             float* __restrict__ out) {
    extern __shared__ __half smh[];
    __half* Ws = smh;                         // 128 x LDH halves
    __half* xs = smh + 128 * LDH;             // 64 x LDH halves
    float*  fs = (float*)(xs + MROWS * LDH);  // 64 x LDH floats
    int tid = threadIdx.x, w = tid >> 5;
    int row0 = blockIdx.x * MROWS;
    int rw = w & 3, ch = w >> 2;

    // stage W1 and x
    for (int i = tid; i < 128 * 128; i += 256)
        Ws[(i >> 7) * LDH + (i & 127)] = W1h[i];
    for (int i = tid; i < MROWS * 16; i += 256) {     // uint4 = 8 halves
        int r = i >> 4, c8 = i & 15, gr = row0 + r;
        uint4 v = make_uint4(0u, 0u, 0u, 0u);
        if (gr < N_NODES) v = *(const uint4*)(x + gr * D + c8 * 8);
        *(uint4*)(xs + r * LDH + c8 * 8) = v;
    }
    __syncthreads();

    // gemm1: t = x @ W1
    wmma::fragment<wmma::accumulator, 16, 16, 16, float> acc[4];
    #pragma unroll
    for (int j = 0; j < 4; j++) wmma::fill_fragment(acc[j], 0.0f);
    #pragma unroll
    for (int k0 = 0; k0 < 128; k0 += 16) {
        wmma::fragment<wmma::matrix_a, 16, 16, 16, __half, wmma::row_major> af;
        wmma::load_matrix_sync(af, xs + rw * 16 * LDH + k0, LDH);
        #pragma unroll
        for (int j = 0; j < 4; j++) {
            wmma::fragment<wmma::matrix_b, 16, 16, 16, __half, wmma::row_major> bf;
            wmma::load_matrix_sync(bf, Ws + k0 * LDH + ch * 64 + j * 16, LDH);
            wmma::mma_sync(acc[j], af, bf, acc[j]);
        }
    }
    #pragma unroll
    for (int j = 0; j < 4; j++)
        wmma::store_matrix_sync(fs + rw * 16 * LDH + ch * 64 + j * 16, acc[j], LDH,
                                wmma::mem_row_major);
    __syncthreads();

    // gelu(t + b1) -> xs (fp16), and stage W2
    for (int i = tid; i < MROWS * 128; i += 256) {
        int r = i >> 7, c = i & 127;
        xs[r * LDH + c] = __float2half_rn(gelu_exact(fs[r * LDH + c] + b1[c]));
    }
    for (int i = tid; i < 128 * 128; i += 256)
        Ws[(i >> 7) * LDH + (i & 127)] = W2h[i];
    __syncthreads();

    // gemm2: out = t @ W2
    #pragma unroll
    for (int j = 0; j < 4; j++) wmma::fill_fragment(acc[j], 0.0f);
    #pragma unroll
    for (int k0 = 0; k0 < 128; k0 += 16) {
        wmma::fragment<wmma::matrix_a, 16, 16, 16, __half, wmma::row_major> af;
        wmma::load_matrix_sync(af, xs + rw * 16 * LDH + k0, LDH);
        #pragma unroll
        for (int j = 0; j < 4; j++) {
            wmma::fragment<wmma::matrix_b, 16, 16, 16, __half, wmma::row_major> bf;
            wmma::load_matrix_sync(bf, Ws + k0 * LDH + ch * 64 + j * 16, LDH);
            wmma::mma_sync(acc[j], af, bf, acc[j]);
        }
    }
    #pragma unroll
    for (int j = 0; j < 4; j++)
        wmma::store_matrix_sync(fs + rw * 16 * LDH + ch * 64 + j * 16, acc[j], LDH,
                                wmma::mem_row_major);
    __syncthreads();

    for (int i = tid; i < MROWS * 128; i += 256) {
        int r = i >> 7, c = i & 127, gr = row0 + r;
        if (gr < N_NODES) out[gr * D + c] = fs[r * LDH + c] + b2[c];
    }
}

// ---------------- launch ----------------
extern "C" void kernel_launch(void* const* d_in, const int* in_sizes, int n_in,
                              void* d_out, int out_size) {
    const float* feat  = (const float*)d_in[0];
    const int*   e_ft  = (const int*)  d_in[1];
    const int*   src   = (const int*)  d_in[2];
    const int*   dst   = (const int*)  d_in[3];
    const float* emb   = (const float*)d_in[4];
    const float* We1   = (const float*)d_in[5];
    const float* be1   = (const float*)d_in[6];
    const float* We2   = (const float*)d_in[7];
    const float* be2   = (const float*)d_in[8];
    const float* W1    = (const float*)d_in[9];
    const float* b1    = (const float*)d_in[10];
    const float* W2    = (const float*)d_in[11];
    const float* b2    = (const float*)d_in[12];
    float* out = (float*)d_out;

    k_zero<<<(N_NODES + 255) / 256, 256>>>();                           // 0
    k_deg<<<(N_EDGES + 255) / 256, 256>>>(src, dst);                    // 1
    k_scan<<<1, 1024>>>();                                              // 2 (+norms)
    k_scatter<<<(N_EDGES + 255) / 256, 256>>>(src, dst, e_ft);          // 3  <- profiled
    k_cvtgate<<<CB + 129, 256>>>(feat, W1, W2, emb, We1, be1, We2, be2);// 4

    __half *hA = nullptr, *hB = nullptr, *w1h = nullptr, *w2h = nullptr;
    float2 *abZ = nullptr, *abH = nullptr;
    cudaGetSymbolAddress((void**)&hA, g_h16A);
    cudaGetSymbolAddress((void**)&hB, g_h16B);
    cudaGetSymbolAddress((void**)&abZ, g_abZ);
    cudaGetSymbolAddress((void**)&abH, g_abH);
    cudaGetSymbolAddress((void**)&w1h, g_W1h);
    cudaGetSymbolAddress((void**)&w2h, g_W2h);

    const __half* zin = hA;       // z0 in buffer A
    __half* hout = hB;
    int hop_blocks = (N_NODES * 32 + 255) / 256;
    for (int k = 0; k < K_HOPS; k++) {
        const float2* ab = (k == K_HOPS - 1) ? abH : abZ;
        k_hop<<<hop_blocks, 256>>>(zin, hout, ab);
        zin  = hout;
        hout = (hout == hA) ? hB : hA;
    }

    size_t smem_bytes = (size_t)(128 * LDH + MROWS * LDH) * sizeof(__half)
                      + (size_t)(MROWS * LDH) * sizeof(float);
    cudaFuncSetAttribute(k_mlp, cudaFuncAttributeMaxDynamicSharedMemorySize, (int)smem_bytes);
    k_mlp<<<(N_NODES + MROWS - 1) / MROWS, 256, smem_bytes>>>(zin, w1h, b1, w2h, b2, out);
}